// round 16
// baseline (speedup 1.0000x reference)
#include <cuda_runtime.h>
#include <math.h>
#include <stdint.h>

#define TPB 256
#define SP_GRID 296
#define EF_GRID 444

#define EMAX 3400000

typedef unsigned long long u64;

__device__ float g_deg[131072];
__device__ int   g_perm2[4 * EMAX];   // per-type segments (one-pass sort)
__device__ int   g_cursor[8];
__device__ int   g_bound[4];          // cumulative padded tile counts

// ---- packed f32x2 helpers ----
__device__ __forceinline__ u64 pack2(float lo, float hi) {
    u64 r; asm("mov.b64 %0,{%1,%2};" : "=l"(r) : "f"(lo), "f"(hi)); return r;
}
__device__ __forceinline__ float2 unpack2(u64 v) {
    float2 f; asm("mov.b64 {%0,%1},%2;" : "=f"(f.x), "=f"(f.y) : "l"(v)); return f;
}
__device__ __forceinline__ u64 add2(u64 a, u64 b) {
    u64 d; asm("add.rn.f32x2 %0,%1,%2;" : "=l"(d) : "l"(a), "l"(b)); return d;
}
__device__ __forceinline__ u64 sub2(u64 a, u64 b) {
    u64 d; asm("sub.rn.f32x2 %0,%1,%2;" : "=l"(d) : "l"(a), "l"(b)); return d;
}
__device__ __forceinline__ u64 mul2(u64 a, u64 b) {
    u64 d; asm("mul.rn.f32x2 %0,%1,%2;" : "=l"(d) : "l"(a), "l"(b)); return d;
}
__device__ __forceinline__ u64 fma2(u64 a, u64 b, u64 c) {
    u64 d; asm("fma.rn.f32x2 %0,%1,%2,%3;" : "=l"(d) : "l"(a), "l"(b), "l"(c)); return d;
}
__device__ __forceinline__ float tanhf_hw(float x) {
    float t; asm("tanh.approx.f32 %0,%1;" : "=f"(t) : "f"(x)); return t;
}
__device__ __forceinline__ u64 gelu2(u64 x, u64 c0, u64 c1, u64 h2) {
    u64 x2 = mul2(x, x);
    u64 w  = fma2(x2, c1, c0);
    u64 u  = mul2(x, w);
    float2 uf = unpack2(u);
    u64 t  = pack2(tanhf_hw(uf.x), tanhf_hw(uf.y));
    u64 tp = fma2(t, h2, h2);
    return mul2(x, tp);
}
__device__ __forceinline__ void st_cs64(float* p, u64 v) {
    asm volatile("st.global.cs.b64 [%0],%1;" :: "l"(p), "l"(v) : "memory");
}

__device__ __forceinline__ uint32_t to_tf32(float f) {
    uint32_t u;
    asm("cvt.rna.tf32.f32 %0, %1;" : "=r"(u) : "f"(f));
    return u;
}
__device__ __forceinline__ void mma_tf32(float& d0, float& d1, float& d2, float& d3,
                                         uint32_t a0, uint32_t a1, uint32_t a2, uint32_t a3,
                                         uint32_t b0, uint32_t b1) {
    asm("mma.sync.aligned.m16n8k8.row.col.f32.tf32.tf32.f32 "
        "{%0,%1,%2,%3}, {%4,%5,%6,%7}, {%8,%9}, {%0,%1,%2,%3};"
        : "+f"(d0), "+f"(d1), "+f"(d2), "+f"(d3)
        : "r"(a0), "r"(a1), "r"(a2), "r"(a3), "r"(b0), "r"(b1));
}

__device__ __forceinline__ int tile_base(int tile, int b0, int b1, int b2) {
    int ty = (tile >= b0) + (tile >= b1) + (tile >= b2);
    int ts = (ty == 0) ? 0 : ((ty == 1) ? b0 : ((ty == 2) ? b1 : b2));
    return ty * EMAX + ((tile - ts) << 4);
}

// ---------------- zero pos_out accumulator + degree (vectorized) ----------------
__global__ void k_zero(float* __restrict__ pos_out, int n) {
    int i = blockIdx.x * blockDim.x + threadIdx.x;
    float4 z = make_float4(0.f, 0.f, 0.f, 0.f);
    if (i < n * 8) reinterpret_cast<float4*>(pos_out)[i] = z;
    int nd4 = n >> 2;
    if (i < nd4) reinterpret_cast<float4*>(g_deg)[i] = z;
    if (i < (n & 3)) g_deg[(nd4 << 2) + i] = 0.0f;
}

// ---------------- xn bin-normalize + dst degree count ----------------
__global__ void k_xn_deg(const float* __restrict__ x, float* __restrict__ out_x,
                         const int* __restrict__ ei, int n, int E) {
    int i = blockIdx.x * blockDim.x + threadIdx.x;
    if (i < E) atomicAdd(&g_deg[ei[E + i]], 1.0f);
    if (i >= n * 35) return;
    float v = x[i];
    int c = i % 35;
    float lo = 0.f, hi = 0.f;
    bool bin = true;
    switch (c) {
        case 23: lo = -4.5f; hi = 4.5f;   break;
        case 24: lo = -2.0f; hi = 2.0f;   break;
        case 25: lo = 75.0f; hi = 204.0f; break;
        case 26: lo = 60.0f; hi = 230.0f; break;
        case 32: lo = 0.0f;  hi = 1.0f;   break;
        case 34: lo = 0.0f;  hi = 100.0f; break;
        default: bin = false; break;
    }
    if (bin) {
        float vc = fminf(fmaxf(v, lo), hi);
        float vn = (vc - lo) / (hi - lo + 1e-6f);
        v = floorf(vn * 10.0f) / 10.0f;
    }
    out_x[i] = v;
}

// ---------------- ONE-PASS type sort into per-type segments ----------------
__global__ void k_sort(const int* __restrict__ et, int E) {
    __shared__ int s_cnt[8];
    __shared__ int s_base[8];
    int tid = threadIdx.x;
    if (tid < 8) s_cnt[tid] = 0;
    __syncthreads();
    int i = blockIdx.x * blockDim.x + tid;
    int t = (i < E) ? et[i] : 5;
    unsigned m = __match_any_sync(0xffffffffu, t);
    int lane = tid & 31;
    int leader = __ffs(m) - 1;
    int rgrp = __popc(m & ((1u << lane) - 1));
    int base = 0;
    if (lane == leader) base = atomicAdd(&s_cnt[t & 7], __popc(m));
    base = __shfl_sync(0xffffffffu, base, leader);
    int myrank = base + rgrp;
    __syncthreads();
    if (tid < 4) s_base[tid] = atomicAdd(&g_cursor[tid], s_cnt[tid]);
    __syncthreads();
    if (i < E && t < 4) g_perm2[t * EMAX + s_base[t] + myrank] = i;
}

__global__ void k_pad() {
    if (threadIdx.x == 0) {
        int s = 0;
        for (int t = 0; t < 4; t++) {
            int cnt = g_cursor[t];
            int pt = (cnt + 15) >> 4;
            for (int i = cnt; i < (pt << 4); i++) g_perm2[t * EMAX + i] = -1;
            s += pt;
            g_bound[t] = s;
        }
    }
}

// ---------------- spatial encoder (unchanged from R15) ----------------
__global__ __launch_bounds__(TPB, 2) void k_spatial(
    const float* __restrict__ pos,
    const float* __restrict__ w1, const float* __restrict__ b1,
    const float* __restrict__ lng, const float* __restrict__ lnb,
    const float* __restrict__ w2, const float* __restrict__ b2,
    const int* __restrict__ ei, int E,
    float* __restrict__ pos_out)
{
    __shared__ __align__(16) float sp[224];
    __shared__ uint32_t wt2[32 * 36];
    __shared__ __align__(16) float astg[8 * 576];

    float* sw1 = sp;
    float* sb1 = sp + 96;
    float* sg  = sp + 128;
    float* sb  = sp + 160;
    float* sb2 = sp + 192;
    for (int i = threadIdx.x; i < 224; i += TPB) {
        float v;
        if      (i < 96)  v = w1[i];
        else if (i < 128) v = b1[i - 96];
        else if (i < 160) v = lng[i - 128];
        else if (i < 192) v = lnb[i - 160];
        else              v = b2[i - 192];
        sp[i] = v;
    }
    for (int i = threadIdx.x; i < 1024; i += TPB) {
        int k = i >> 5, n = i & 31;
        wt2[n * 36 + k] = to_tf32(w2[i]);
    }
    __syncthreads();

    const u64 GC0 = pack2(0.7978845608028654f, 0.7978845608028654f);
    const u64 GC1 = pack2(0.0356774081363f, 0.0356774081363f);
    const u64 GH  = pack2(0.5f, 0.5f);

    int wid  = threadIdx.x >> 5;
    int lane = threadIdx.x & 31;
    int ntiles = (E + 15) >> 4;
    int gw = blockIdx.x * (TPB / 32) + wid;
    int nw = gridDim.x * (TPB / 32);
    int tpw = (ntiles + nw - 1) / nw;
    int tile0 = gw * tpw;
    int tile1 = min(ntiles, tile0 + tpw);

    float* As = astg + wid * 576;
    int r = lane >> 2, c = lane & 3;
    int e_local = lane >> 1;
    int half = lane & 1;
    int j0 = half * 16;
    bool evenc = (c & 1) == 0;
    int myrow = evenc ? r : (r + 8);
    int col0b = (c & ~1) * 2;

    uint32_t B[4][4][2];
    #pragma unroll
    for (int tt = 0; tt < 4; tt++) {
        int nn = r + 8 * tt;
        #pragma unroll
        for (int kk = 0; kk < 4; kk++) {
            int k0 = c + 8 * kk;
            B[tt][kk][0] = wt2[nn * 36 + k0];
            B[tt][kk][1] = wt2[nn * 36 + k0 + 4];
        }
    }

    int sc = 0, dc = 0, sn = 0, dn = 0;
    float psx = 0, psy = 0, psz = 0, pdx = 0, pdy = 0, pdz = 0;
    if (tile0 < tile1) {
        int me = (tile0 << 4) + e_local;
        bool ev = me < E;
        sc = ev ? ei[me] : 0;
        dc = ev ? ei[E + me] : 0;
    }
    if (tile0 + 1 < tile1) {
        int me = ((tile0 + 1) << 4) + e_local;
        bool ev = me < E;
        sn = ev ? ei[me] : 0;
        dn = ev ? ei[E + me] : 0;
    }
    if (tile0 < tile1) {
        psx = pos[sc * 3 + 0]; psy = pos[sc * 3 + 1]; psz = pos[sc * 3 + 2];
        pdx = pos[dc * 3 + 0]; pdy = pos[dc * 3 + 1]; pdz = pos[dc * 3 + 2];
    }

    for (int tile = tile0; tile < tile1; tile++) {
        int i0 = tile << 4;

        float rx = pdx - psx;
        float ry = pdy - psy;
        float rz = pdz - psz;
        int cur_dst = dc;

        sc = sn; dc = dn;
        if (tile + 2 < tile1) {
            int me = ((tile + 2) << 4) + e_local;
            bool ev = me < E;
            sn = ev ? ei[me] : 0;
            dn = ev ? ei[E + me] : 0;
        }
        if (tile + 1 < tile1) {
            psx = pos[sc * 3 + 0]; psy = pos[sc * 3 + 1]; psz = pos[sc * 3 + 2];
            pdx = pos[dc * 3 + 0]; pdy = pos[dc * 3 + 1]; pdz = pos[dc * 3 + 2];
        }

        float dist = sqrtf(rx * rx + ry * ry + rz * rz);
        float inv  = 1.0f / (dist + 1e-6f);
        u64 rx2 = pack2(rx * inv, rx * inv);
        u64 ry2 = pack2(ry * inv, ry * inv);
        u64 rz2 = pack2(rz * inv, rz * inv);

        u64 H[8];
        u64 M2 = 0;
        #pragma unroll
        for (int p = 0; p < 8; p++) {
            int j = j0 + 2 * p;
            u64 t = fma2(rz2, *(const u64*)&sw1[64 + j], *(const u64*)&sb1[j]);
            t = fma2(ry2, *(const u64*)&sw1[32 + j], t);
            t = fma2(rx2, *(const u64*)&sw1[j], t);
            H[p] = t;
            M2 = (p == 0) ? t : add2(M2, t);
        }
        float2 mf = unpack2(M2);
        float m = mf.x + mf.y;
        m += __shfl_xor_sync(0xffffffffu, m, 1);
        m *= (1.0f / 32.0f);
        u64 m2 = pack2(m, m);
        u64 Q2 = 0;
        #pragma unroll
        for (int p = 0; p < 8; p++) {
            u64 d = sub2(H[p], m2);
            H[p] = d;
            Q2 = (p == 0) ? mul2(d, d) : fma2(d, d, Q2);
        }
        float2 qf = unpack2(Q2);
        float var = qf.x + qf.y;
        var += __shfl_xor_sync(0xffffffffu, var, 1);
        var *= (1.0f / 32.0f);
        float rstd = rsqrtf(var + 1e-5f);
        u64 rs2 = pack2(rstd, rstd);
        #pragma unroll
        for (int p = 0; p < 8; p++) {
            int j = j0 + 2 * p;
            u64 t = fma2(mul2(H[p], rs2), *(const u64*)&sg[j], *(const u64*)&sb[j]);
            H[p] = gelu2(t, GC0, GC1, GH);
        }

        #pragma unroll
        for (int q = 0; q < 4; q++) {
            ulonglong2 v; v.x = H[2 * q]; v.y = H[2 * q + 1];
            *reinterpret_cast<ulonglong2*>(As + e_local * 36 + j0 + 4 * q) = v;
        }
        __syncwarp();

        uint32_t A[4][4];
        #pragma unroll
        for (int kk = 0; kk < 4; kk++) {
            A[kk][0] = to_tf32(As[r * 36 + c + 8 * kk]);
            A[kk][1] = to_tf32(As[(r + 8) * 36 + c + 8 * kk]);
            A[kk][2] = to_tf32(As[r * 36 + c + 4 + 8 * kk]);
            A[kk][3] = to_tf32(As[(r + 8) * 36 + c + 4 + 8 * kk]);
        }
        __syncwarp();

        float C[4][4];
        #pragma unroll
        for (int tt = 0; tt < 4; tt++) { C[tt][0] = C[tt][1] = C[tt][2] = C[tt][3] = 0.0f; }
        #pragma unroll
        for (int tt = 0; tt < 4; tt++) {
            #pragma unroll
            for (int kk = 0; kk < 4; kk++)
                mma_tf32(C[tt][0], C[tt][1], C[tt][2], C[tt][3],
                         A[kk][0], A[kk][1], A[kk][2], A[kk][3],
                         B[tt][kk][0], B[tt][kk][1]);
        }

        int dst_row = __shfl_sync(0xffffffffu, cur_dst, 2 * myrow);
        bool row_ok = (i0 + myrow) < E;
        float* op = pos_out + (size_t)dst_row * 32;

        #pragma unroll
        for (int tt = 0; tt < 4; tt++) {
            int col = 2 * c + 8 * tt;
            float bx = sb2[col], by = sb2[col + 1];
            C[tt][0] += bx; C[tt][1] += by;
            C[tt][2] += bx; C[tt][3] += by;

            float s0 = evenc ? C[tt][2] : C[tt][0];
            float s1 = evenc ? C[tt][3] : C[tt][1];
            float r0 = __shfl_xor_sync(0xffffffffu, s0, 1);
            float r1 = __shfl_xor_sync(0xffffffffu, s1, 1);
            float v0 = evenc ? C[tt][0] : r0;
            float v1 = evenc ? C[tt][1] : r1;
            float v2 = evenc ? r0 : C[tt][2];
            float v3 = evenc ? r1 : C[tt][3];
            if (row_ok) {
                asm volatile("red.global.add.v4.f32 [%0], {%1,%2,%3,%4};"
                             :: "l"(op + col0b + 8 * tt), "f"(v0), "f"(v1), "f"(v2), "f"(v3)
                             : "memory");
            }
        }
    }
}

// ---------------- edge processor: 3 blocks/SM, 3-pass epilogue (no P arrays) ----------------
__global__ __launch_bounds__(TPB, 3) void k_ef(
    const float* __restrict__ ea,
    const float* __restrict__ ew, const float* __restrict__ eb,
    const float* __restrict__ eg, const float* __restrict__ ebt,
    float* __restrict__ out)
{
    __shared__ uint32_t wt[4 * 1280];
    __shared__ __align__(16) float prm[3 * 4 * 72];
    __shared__ __align__(16) float astg[8 * 320];

    if (blockIdx.x == 0 && threadIdx.x < 8) g_cursor[threadIdx.x] = 0;

    for (int i = threadIdx.x; i < 4096; i += TPB) {
        int t = i >> 10, r = i & 1023, k = r >> 6, n = r & 63;
        wt[t * 1280 + n * 20 + k] = to_tf32(ew[i]);
    }
    for (int i = threadIdx.x; i < 256; i += TPB) {
        int t = i >> 6, j = i & 63;
        prm[t * 72 + j]       = eb[i];
        prm[288 + t * 72 + j] = eg[i];
        prm[576 + t * 72 + j] = ebt[i];
    }
    __syncthreads();

    const u64 GC0 = pack2(0.7978845608028654f, 0.7978845608028654f);
    const u64 GC1 = pack2(0.0356774081363f, 0.0356774081363f);
    const u64 GH  = pack2(0.5f, 0.5f);

    int b0 = g_bound[0], b1v = g_bound[1], b2v = g_bound[2];
    int ntiles = g_bound[3];

    int wid  = threadIdx.x >> 5;
    int lane = threadIdx.x & 31;
    int gw   = blockIdx.x * (TPB / 32) + wid;
    int nw   = gridDim.x * (TPB / 32);
    int tpw  = (ntiles + nw - 1) / nw;
    int tile0 = gw * tpw;
    int tile1 = min(ntiles, tile0 + tpw);

    float* As = astg + wid * 320;
    int r = lane >> 2, c = lane & 3;

    uint32_t B[8][2][2];
    int tprev = -1;

    int pe0c = 0, pe1c = 0, pe0n = 0, pe1n = 0;
    float4 v0, v1;
    if (tile0 < tile1) {
        int ba = tile_base(tile0, b0, b1v, b2v);
        pe0c = g_perm2[ba + r];
        pe1c = g_perm2[ba + 8 + r];
    }
    if (tile0 + 1 < tile1) {
        int ba = tile_base(tile0 + 1, b0, b1v, b2v);
        pe0n = g_perm2[ba + r];
        pe1n = g_perm2[ba + 8 + r];
    }
    if (tile0 < tile1) {
        size_t e0 = (size_t)max(pe0c, 0), e1 = (size_t)max(pe1c, 0);
        v0 = *reinterpret_cast<const float4*>(ea + e0 * 16 + c * 4);
        v1 = *reinterpret_cast<const float4*>(ea + e1 * 16 + c * 4);
    }

    for (int tile = tile0; tile < tile1; tile++) {
        int ty = (tile >= b0) + (tile >= b1v) + (tile >= b2v);
        if (ty != tprev) {
            tprev = ty;
            #pragma unroll
            for (int tt = 0; tt < 8; tt++) {
                int n = r + 8 * tt;
                #pragma unroll
                for (int kk = 0; kk < 2; kk++) {
                    int k0 = c + 8 * kk;
                    B[tt][kk][0] = wt[ty * 1280 + n * 20 + k0];
                    B[tt][kk][1] = wt[ty * 1280 + n * 20 + k0 + 4];
                }
            }
        }

        *reinterpret_cast<float4*>(As + r * 20 + c * 4)       = v0;
        *reinterpret_cast<float4*>(As + (r + 8) * 20 + c * 4) = v1;
        __syncwarp();

        uint32_t A[2][4];
        #pragma unroll
        for (int kk = 0; kk < 2; kk++) {
            A[kk][0] = to_tf32(As[r * 20 + c + 8 * kk]);
            A[kk][1] = to_tf32(As[(r + 8) * 20 + c + 8 * kk]);
            A[kk][2] = to_tf32(As[r * 20 + c + 4 + 8 * kk]);
            A[kk][3] = to_tf32(As[(r + 8) * 20 + c + 4 + 8 * kk]);
        }
        __syncwarp();

        int cur0 = pe0c, cur1 = pe1c;

        pe0c = pe0n; pe1c = pe1n;
        if (tile + 2 < tile1) {
            int ba = tile_base(tile + 2, b0, b1v, b2v);
            pe0n = g_perm2[ba + r];
            pe1n = g_perm2[ba + 8 + r];
        }
        if (tile + 1 < tile1) {
            size_t e0 = (size_t)max(pe0c, 0), e1 = (size_t)max(pe1c, 0);
            v0 = *reinterpret_cast<const float4*>(ea + e0 * 16 + c * 4);
            v1 = *reinterpret_cast<const float4*>(ea + e1 * 16 + c * 4);
        }

        float C[8][4];
        #pragma unroll
        for (int tt = 0; tt < 8; tt++) { C[tt][0] = C[tt][1] = C[tt][2] = C[tt][3] = 0.0f; }
        #pragma unroll
        for (int tt = 0; tt < 8; tt++) {
            #pragma unroll
            for (int kk = 0; kk < 2; kk++)
                mma_tf32(C[tt][0], C[tt][1], C[tt][2], C[tt][3],
                         A[kk][0], A[kk][1], A[kk][2], A[kk][3],
                         B[tt][kk][0], B[tt][kk][1]);
        }

        const float* bias = prm + ty * 72;
        const float* gam  = prm + 288 + ty * 72;
        const float* bet  = prm + 576 + ty * 72;

        // pass 1: sums (bias-add recomputed per pass; no P arrays -> lower reg pressure)
        u64 S0 = 0, S1 = 0;
        #pragma unroll
        for (int tt = 0; tt < 8; tt++) {
            int col = 2 * c + 8 * tt;
            u64 bv = *(const u64*)(bias + col);
            u64 p0 = add2(pack2(C[tt][0], C[tt][1]), bv);
            u64 p1 = add2(pack2(C[tt][2], C[tt][3]), bv);
            S0 = (tt == 0) ? p0 : add2(S0, p0);
            S1 = (tt == 0) ? p1 : add2(S1, p1);
        }
        float2 s0f = unpack2(S0), s1f = unpack2(S1);
        float s0 = s0f.x + s0f.y, s1 = s1f.x + s1f.y;
        s0 += __shfl_xor_sync(0xffffffffu, s0, 1);
        s0 += __shfl_xor_sync(0xffffffffu, s0, 2);
        s1 += __shfl_xor_sync(0xffffffffu, s1, 1);
        s1 += __shfl_xor_sync(0xffffffffu, s1, 2);
        float m0 = s0 * (1.0f / 64.0f), m1 = s1 * (1.0f / 64.0f);
        u64 m02 = pack2(m0, m0), m12 = pack2(m1, m1);

        // pass 2: variance
        u64 Q0 = 0, Q1 = 0;
        #pragma unroll
        for (int tt = 0; tt < 8; tt++) {
            int col = 2 * c + 8 * tt;
            u64 bv = *(const u64*)(bias + col);
            u64 d0 = sub2(add2(pack2(C[tt][0], C[tt][1]), bv), m02);
            u64 d1 = sub2(add2(pack2(C[tt][2], C[tt][3]), bv), m12);
            Q0 = (tt == 0) ? mul2(d0, d0) : fma2(d0, d0, Q0);
            Q1 = (tt == 0) ? mul2(d1, d1) : fma2(d1, d1, Q1);
        }
        float2 q0f = unpack2(Q0), q1f = unpack2(Q1);
        float q0 = q0f.x + q0f.y, q1 = q1f.x + q1f.y;
        q0 += __shfl_xor_sync(0xffffffffu, q0, 1);
        q0 += __shfl_xor_sync(0xffffffffu, q0, 2);
        q1 += __shfl_xor_sync(0xffffffffu, q1, 1);
        q1 += __shfl_xor_sync(0xffffffffu, q1, 2);
        float rs0 = rsqrtf(q0 * (1.0f / 64.0f) + 1e-5f);
        float rs1 = rsqrtf(q1 * (1.0f / 64.0f) + 1e-5f);
        u64 rs02 = pack2(rs0, rs0);
        u64 rs12 = pack2(rs1, rs1);

        // pass 3: normalize + GELU + streaming store
        #pragma unroll
        for (int tt = 0; tt < 8; tt++) {
            int col = 2 * c + 8 * tt;
            u64 bv2 = *(const u64*)(bias + col);
            u64 gv  = *(const u64*)(gam + col);
            u64 btv = *(const u64*)(bet + col);
            if (cur0 >= 0) {
                u64 d = sub2(add2(pack2(C[tt][0], C[tt][1]), bv2), m02);
                u64 t = fma2(mul2(d, rs02), gv, btv);
                st_cs64(out + (size_t)cur0 * 64 + col, gelu2(t, GC0, GC1, GH));
            }
            if (cur1 >= 0) {
                u64 d = sub2(add2(pack2(C[tt][2], C[tt][3]), bv2), m12);
                u64 t = fma2(mul2(d, rs12), gv, btv);
                st_cs64(out + (size_t)cur1 * 64 + col, gelu2(t, GC0, GC1, GH));
            }
        }
    }
}

// ---------------- finalize scatter-mean (vectorized, streaming) ----------------
__global__ void k_fin(float* __restrict__ pos_out, int n) {
    int i = blockIdx.x * blockDim.x + threadIdx.x;
    if (i >= n * 8) return;                 // 4 floats per thread
    float d = fmaxf(g_deg[i >> 3], 1.0f);
    float inv = 1.0f / d;
    float4 v = reinterpret_cast<float4*>(pos_out)[i];
    v.x *= inv; v.y *= inv; v.z *= inv; v.w *= inv;
    reinterpret_cast<float4*>(pos_out)[i] = v;
}

extern "C" void kernel_launch(void* const* d_in, const int* in_sizes, int n_in,
                              void* d_out, int out_size) {
    const float* x      = (const float*)d_in[0];
    const float* pos    = (const float*)d_in[1];
    const float* ea     = (const float*)d_in[2];
    const float* sp_w1  = (const float*)d_in[3];
    const float* sp_b1  = (const float*)d_in[4];
    const float* sp_lng = (const float*)d_in[5];
    const float* sp_lnb = (const float*)d_in[6];
    const float* sp_w2  = (const float*)d_in[7];
    const float* sp_b2  = (const float*)d_in[8];
    const float* e_w    = (const float*)d_in[9];
    const float* e_b    = (const float*)d_in[10];
    const float* e_lng  = (const float*)d_in[11];
    const float* e_lnb  = (const float*)d_in[12];
    const int*   ei     = (const int*)d_in[13];
    const int*   et     = (const int*)d_in[14];

    int n = in_sizes[0] / 35;
    int E = in_sizes[2] / 16;

    float* out     = (float*)d_out;
    float* out_x   = out;
    float* out_pos = out + (size_t)n * 35;
    float* out_ef  = out_pos + (size_t)n * 32;

    static cudaStream_t sB = nullptr, sC = nullptr;
    static cudaEvent_t  evO = nullptr, evZ = nullptr, evH = nullptr, evB = nullptr;
    if (sB == nullptr) {
        cudaStreamCreateWithFlags(&sB, cudaStreamNonBlocking);
        cudaStreamCreateWithFlags(&sC, cudaStreamNonBlocking);
        cudaEventCreateWithFlags(&evO, cudaEventDisableTiming);
        cudaEventCreateWithFlags(&evZ, cudaEventDisableTiming);
        cudaEventCreateWithFlags(&evH, cudaEventDisableTiming);
        cudaEventCreateWithFlags(&evB, cudaEventDisableTiming);
    }

    cudaEventRecord(evO, 0);

    // Branch B: one-pass sort -> pad -> edge processor
    cudaStreamWaitEvent(sB, evO, 0);
    int sb = (E + 255) / 256;
    k_sort<<<sb, 256, 0, sB>>>(et, E);
    k_pad<<<1, 32, 0, sB>>>();
    k_ef<<<EF_GRID, TPB, 0, sB>>>(ea, e_w, e_b, e_lng, e_lnb, out_ef);
    cudaEventRecord(evB, sB);

    // Main: zero accumulators, then spatial
    int zb4 = (n * 8 + 255) / 256;
    k_zero<<<zb4, 256>>>(out_pos, n);
    cudaEventRecord(evZ, 0);

    // Branch C: xn + degree count
    cudaStreamWaitEvent(sC, evZ, 0);
    int xb = (n * 35 + 255) / 256;
    k_xn_deg<<<xb, 256, 0, sC>>>(x, out_x, ei, n, E);
    cudaEventRecord(evH, sC);

    k_spatial<<<SP_GRID, TPB>>>(pos, sp_w1, sp_b1, sp_lng, sp_lnb, sp_w2, sp_b2,
                                ei, E, out_pos);
    cudaStreamWaitEvent(0, evH, 0);
    k_fin<<<zb4, 256>>>(out_pos, n);

    cudaStreamWaitEvent(0, evB, 0);
}